// round 1
// baseline (speedup 1.0000x reference)
#include <cuda_runtime.h>
#include <math.h>

#define BATCH 8
#define SEQ   2048
#define DIM   768
#define MTOT  (BATCH*SEQ)

// Static device scratch (allocation-free per harness rules)
__device__ float g_Q[(size_t)MTOT * DIM];
__device__ float g_K[(size_t)MTOT * DIM];
__device__ float g_V[(size_t)MTOT * DIM];
__device__ float g_P[(size_t)BATCH * SEQ * SEQ];

#define BM 64
#define BN 64
#define BK 16

// C[M,N] = scale * A[M,K] @ B[N,K]^T   (both row-major, K contiguous), batched over z
__global__ __launch_bounds__(256) void gemm_nt(
    const float* __restrict__ A, const float* __restrict__ Bm, float* __restrict__ C,
    int M, int N, int K, long sA, long sB, long sC, float scale)
{
    __shared__ float As[BK][BM];
    __shared__ float Bs[BK][BN];

    const float* Ab = A  + (long)blockIdx.z * sA;
    const float* Bb = Bm + (long)blockIdx.z * sB;
    float*       Cb = C  + (long)blockIdx.z * sC;

    const int t  = threadIdx.x;
    const int tx = t & 15;        // 0..15 -> output col group
    const int ty = t >> 4;        // 0..15 -> output row group
    const int rowBase = blockIdx.y * BM;
    const int colBase = blockIdx.x * BN;

    const int lr  = t >> 2;        // 0..63  tile row for loads
    const int lc4 = (t & 3) * 4;   // 0,4,8,12 k-offset for loads

    float acc[4][4] = {};

    for (int k0 = 0; k0 < K; k0 += BK) {
        float4 av = *(const float4*)(Ab + (long)(rowBase + lr) * K + k0 + lc4);
        float4 bv = *(const float4*)(Bb + (long)(colBase + lr) * K + k0 + lc4);
        As[lc4 + 0][lr] = av.x; As[lc4 + 1][lr] = av.y;
        As[lc4 + 2][lr] = av.z; As[lc4 + 3][lr] = av.w;
        Bs[lc4 + 0][lr] = bv.x; Bs[lc4 + 1][lr] = bv.y;
        Bs[lc4 + 2][lr] = bv.z; Bs[lc4 + 3][lr] = bv.w;
        __syncthreads();

#pragma unroll
        for (int kk = 0; kk < BK; kk++) {
            float4 a = *(const float4*)&As[kk][ty * 4];
            float4 b = *(const float4*)&Bs[kk][tx * 4];
            float ar[4] = {a.x, a.y, a.z, a.w};
            float br[4] = {b.x, b.y, b.z, b.w};
#pragma unroll
            for (int i = 0; i < 4; i++)
#pragma unroll
                for (int j = 0; j < 4; j++)
                    acc[i][j] += ar[i] * br[j];
        }
        __syncthreads();
    }

#pragma unroll
    for (int i = 0; i < 4; i++) {
        long r = rowBase + ty * 4 + i;
#pragma unroll
        for (int j = 0; j < 4; j++)
            Cb[r * N + colBase + tx * 4 + j] = acc[i][j] * scale;
    }
}

// C[M,N] = A[M,K] @ B[K,N]   (both row-major), batched over z
__global__ __launch_bounds__(256) void gemm_nn(
    const float* __restrict__ A, const float* __restrict__ Bm, float* __restrict__ C,
    int M, int N, int K, long sA, long sB, long sC)
{
    __shared__ float As[BK][BM];
    __shared__ float Bs[BK][BN];

    const float* Ab = A  + (long)blockIdx.z * sA;
    const float* Bb = Bm + (long)blockIdx.z * sB;
    float*       Cb = C  + (long)blockIdx.z * sC;

    const int t  = threadIdx.x;
    const int tx = t & 15;
    const int ty = t >> 4;
    const int rowBase = blockIdx.y * BM;
    const int colBase = blockIdx.x * BN;

    const int lr  = t >> 2;        // A-load row 0..63
    const int lc4 = (t & 3) * 4;   // A-load k offset
    const int br_ = t >> 4;        // B-load k row 0..15
    const int bc4 = (t & 15) * 4;  // B-load col 0..60

    float acc[4][4] = {};

    for (int k0 = 0; k0 < K; k0 += BK) {
        float4 av = *(const float4*)(Ab + (long)(rowBase + lr) * K + k0 + lc4);
        As[lc4 + 0][lr] = av.x; As[lc4 + 1][lr] = av.y;
        As[lc4 + 2][lr] = av.z; As[lc4 + 3][lr] = av.w;
        float4 bv = *(const float4*)(Bb + (long)(k0 + br_) * N + colBase + bc4);
        *(float4*)&Bs[br_][bc4] = bv;
        __syncthreads();

#pragma unroll
        for (int kk = 0; kk < BK; kk++) {
            float4 a = *(const float4*)&As[kk][ty * 4];
            float4 b = *(const float4*)&Bs[kk][tx * 4];
            float ar[4] = {a.x, a.y, a.z, a.w};
            float br[4] = {b.x, b.y, b.z, b.w};
#pragma unroll
            for (int i = 0; i < 4; i++)
#pragma unroll
                for (int j = 0; j < 4; j++)
                    acc[i][j] += ar[i] * br[j];
        }
        __syncthreads();
    }

#pragma unroll
    for (int i = 0; i < 4; i++) {
        long r = rowBase + ty * 4 + i;
#pragma unroll
        for (int j = 0; j < 4; j++)
            Cb[r * N + colBase + tx * 4 + j] = acc[i][j];
    }
}

// In-place row softmax over SEQ columns; one block per row, 256 threads x 8 elems
__global__ __launch_bounds__(256) void softmax_rows(float* __restrict__ P)
{
    __shared__ float red[256];
    float* p = P + (long)blockIdx.x * SEQ;
    const int t = threadIdx.x;

    float v[8];
    float m = -1e30f;
#pragma unroll
    for (int i = 0; i < 8; i++) {
        v[i] = p[t + i * 256];
        m = fmaxf(m, v[i]);
    }
    red[t] = m; __syncthreads();
    for (int s = 128; s > 0; s >>= 1) {
        if (t < s) red[t] = fmaxf(red[t], red[t + s]);
        __syncthreads();
    }
    m = red[0]; __syncthreads();

    float sum = 0.f;
#pragma unroll
    for (int i = 0; i < 8; i++) {
        v[i] = __expf(v[i] - m);
        sum += v[i];
    }
    red[t] = sum; __syncthreads();
    for (int s = 128; s > 0; s >>= 1) {
        if (t < s) red[t] += red[t + s];
        __syncthreads();
    }
    float inv = 1.0f / red[0];
#pragma unroll
    for (int i = 0; i < 8; i++)
        p[t + i * 256] = v[i] * inv;
}

extern "C" void kernel_launch(void* const* d_in, const int* in_sizes, int n_in,
                              void* d_out, int out_size)
{
    const float* x  = (const float*)d_in[0];
    const float* Wq = (const float*)d_in[1];
    const float* Wk = (const float*)d_in[2];
    const float* Wv = (const float*)d_in[3];
    float* out = (float*)d_out;

    float *Q, *K, *V, *P;
    cudaGetSymbolAddress((void**)&Q, g_Q);
    cudaGetSymbolAddress((void**)&K, g_K);
    cudaGetSymbolAddress((void**)&V, g_V);
    cudaGetSymbolAddress((void**)&P, g_P);

    const float scale = 1.0f / sqrtf((float)DIM);
    dim3 thr(256);

    // QKV projections: out[m,e] = sum_d x[m,d] * W[e,d]  -> NT GEMM 16384x768x768
    dim3 gProj(DIM / BN, MTOT / BM, 1);
    gemm_nt<<<gProj, thr>>>(x, Wq, Q, MTOT, DIM, DIM, 0, 0, 0, 1.0f);
    gemm_nt<<<gProj, thr>>>(x, Wk, K, MTOT, DIM, DIM, 0, 0, 0, 1.0f);
    gemm_nt<<<gProj, thr>>>(x, Wv, V, MTOT, DIM, DIM, 0, 0, 0, 1.0f);

    // Scores: per batch, S[q,k] = scale * Q[q,:] . K[k,:]  -> batched NT 2048x2048x768
    dim3 gScore(SEQ / BN, SEQ / BM, BATCH);
    gemm_nt<<<gScore, thr>>>(Q, K, P, SEQ, SEQ, DIM,
                             (long)SEQ * DIM, (long)SEQ * DIM, (long)SEQ * SEQ, scale);

    // Softmax over key axis
    softmax_rows<<<BATCH * SEQ, 256>>>(P);

    // H = A @ V  -> batched NN 2048x768x2048, straight into d_out
    dim3 gAV(DIM / BN, SEQ / BM, BATCH);
    gemm_nn<<<gAV, thr>>>(P, V, out, SEQ, DIM, SEQ,
                          (long)SEQ * SEQ, (long)SEQ * DIM, (long)SEQ * DIM);
}

// round 3
// speedup vs baseline: 2.9837x; 2.9837x over previous
#include <cuda_runtime.h>
#include <cuda_bf16.h>
#include <math.h>
#include <stdint.h>

#define BATCH 8
#define SEQ   2048
#define DIM   768
#define MTOT  (BATCH*SEQ)

// ---------------- static device scratch ----------------
__device__ __nv_bfloat16 g_xh[(size_t)MTOT*DIM],  g_xl[(size_t)MTOT*DIM];
__device__ __nv_bfloat16 g_Wqh[DIM*DIM], g_Wql[DIM*DIM];
__device__ __nv_bfloat16 g_Wkh[DIM*DIM], g_Wkl[DIM*DIM];
__device__ __nv_bfloat16 g_Wvh[DIM*DIM], g_Wvl[DIM*DIM];
__device__ __nv_bfloat16 g_Qh[(size_t)MTOT*DIM], g_Ql[(size_t)MTOT*DIM];
__device__ __nv_bfloat16 g_Kh[(size_t)MTOT*DIM], g_Kl[(size_t)MTOT*DIM];
__device__ __nv_bfloat16 g_Vth[(size_t)DIM*MTOT], g_Vtl[(size_t)DIM*MTOT];
__device__ float         g_P [(size_t)BATCH*SEQ*SEQ];
__device__ __nv_bfloat16 g_Ph[(size_t)BATCH*SEQ*SEQ], g_Pl[(size_t)BATCH*SEQ*SEQ];

// ---------------- tiling ----------------
#define BM 128
#define BN 128
#define BK 32
#define STAGES 4
#define ROWB 80                       // 32 bf16 (64B) + 16B pad: conflict-free ldmatrix
#define TILE_SMEM (128*ROWB)          // 10240 B
#define STAGE_SMEM (4*TILE_SMEM)      // Ah, Al, Bh, Bl = 40960 B
#define SMEM_TOTAL (STAGES*STAGE_SMEM) // 163840 B

// ---------------- PTX helpers ----------------
__device__ __forceinline__ uint32_t smem_u32(const void* p) {
    uint32_t a;
    asm("{ .reg .u64 t; cvta.to.shared.u64 t, %1; cvt.u32.u64 %0, t; }" : "=r"(a) : "l"(p));
    return a;
}
__device__ __forceinline__ void cp_async16(uint32_t saddr, const void* gaddr) {
    asm volatile("cp.async.cg.shared.global [%0], [%1], 16;" :: "r"(saddr), "l"(gaddr));
}
__device__ __forceinline__ void cp_commit() {
    asm volatile("cp.async.commit_group;" ::: "memory");
}
template<int N> __device__ __forceinline__ void cp_wait() {
    asm volatile("cp.async.wait_group %0;" :: "n"(N) : "memory");
}
__device__ __forceinline__ void ldsm4(uint32_t* r, uint32_t addr) {
    asm volatile("ldmatrix.sync.aligned.m8n8.x4.shared.b16 {%0,%1,%2,%3}, [%4];"
                 : "=r"(r[0]), "=r"(r[1]), "=r"(r[2]), "=r"(r[3]) : "r"(addr));
}
__device__ __forceinline__ void mma16816(float* c, const uint32_t* a, const uint32_t* b) {
    asm volatile(
        "mma.sync.aligned.m16n8k16.row.col.f32.bf16.bf16.f32 "
        "{%0,%1,%2,%3}, {%4,%5,%6,%7}, {%8,%9}, {%0,%1,%2,%3};"
        : "+f"(c[0]), "+f"(c[1]), "+f"(c[2]), "+f"(c[3])
        : "r"(a[0]), "r"(a[1]), "r"(a[2]), "r"(a[3]), "r"(b[0]), "r"(b[1]));
}

// ---------------- GEMM: C[M,N] = scale * A[M,K] @ B[N,K]^T (split bf16) ----------------
__global__ void __launch_bounds__(256, 1) gemm_tc(
    const __nv_bfloat16* __restrict__ Ah, const __nv_bfloat16* __restrict__ Al,
    const __nv_bfloat16* __restrict__ Bh, const __nv_bfloat16* __restrict__ Bl,
    float* __restrict__ Cf, __nv_bfloat16* __restrict__ Ch, __nv_bfloat16* __restrict__ Cl,
    int K, int lda, int ldb, int ldc,
    long sA, long sB, long sC, float scale, int mode)
{
    extern __shared__ char smem[];
    const uint32_t sb = smem_u32(smem);
    const int tid  = threadIdx.x;
    const int lane = tid & 31;
    const int wid  = tid >> 5;
    const int wm   = wid & 1;        // 2 warps along M
    const int wn   = wid >> 1;       // 4 warps along N
    const long z = blockIdx.z;

    const __nv_bfloat16* AhB = Ah + z * sA;
    const __nv_bfloat16* AlB = Al + z * sA;
    const __nv_bfloat16* BhB = Bh + z * sB;
    const __nv_bfloat16* BlB = Bl + z * sB;

    const int rowBase = blockIdx.y * BM;
    const int colBase = blockIdx.x * BN;

    // ---- per-thread cp.async source pointers & smem offsets (8 chunks/thread) ----
    const __nv_bfloat16* gsrc[8];
    uint32_t soff[8];
#pragma unroll
    for (int i = 0; i < 8; i++) {
        int tile = i >> 1;                         // 0:Ah 1:Al 2:Bh 3:Bl
        int idx  = tid + (i & 1) * 256;            // 0..511
        int row  = idx >> 2;
        int ch   = idx & 3;
        const __nv_bfloat16* s = (tile == 0) ? AhB : (tile == 1) ? AlB
                               : (tile == 2) ? BhB : BlB;
        int rs = (tile < 2) ? rowBase : colBase;
        int ld = (tile < 2) ? lda : ldb;
        gsrc[i] = s + (long)(rs + row) * ld + ch * 8;
        soff[i] = tile * TILE_SMEM + row * ROWB + ch * 16;
    }

    // ---- per-lane ldmatrix offsets ----
    const int j = lane >> 3, r = lane & 7;
    // A: 16x16 tile, mats [m0,k0],[m8,k0],[m0,k8],[m8,k8]
    const uint32_t aOff = (uint32_t)(wm * 64 + (j & 1) * 8 + r) * ROWB + ((j >> 1) * 8) * 2;
    // B: two n8 tiles per x4, mats [n0,k0],[n0,k8],[n8,k0],[n8,k8]
    const uint32_t bOff = (uint32_t)(wn * 32 + (j >> 1) * 8 + r) * ROWB + ((j & 1) * 8) * 2;

    const int kTiles = K / BK;

    // ---- prologue: fill STAGES-1 stages ----
#pragma unroll
    for (int s = 0; s < STAGES - 1; s++) {
        int k0 = s * BK;
#pragma unroll
        for (int i = 0; i < 8; i++)
            cp_async16(sb + s * STAGE_SMEM + soff[i], gsrc[i] + k0);
        cp_commit();
    }

    float acc[4][4][4];
#pragma unroll
    for (int a = 0; a < 4; a++)
#pragma unroll
        for (int b = 0; b < 4; b++)
#pragma unroll
            for (int q = 0; q < 4; q++) acc[a][b][q] = 0.f;

    for (int kt = 0; kt < kTiles; kt++) {
        cp_wait<STAGES - 2>();
        __syncthreads();

        // issue loads for tile kt+STAGES-1 into the stage freed last iteration
        {
            int ft = kt + STAGES - 1;
            if (ft < kTiles) {
                uint32_t sbase = sb + (ft % STAGES) * STAGE_SMEM;
                int k0 = ft * BK;
#pragma unroll
                for (int i = 0; i < 8; i++)
                    cp_async16(sbase + soff[i], gsrc[i] + k0);
            }
            cp_commit();   // commit every iter (possibly empty) to keep group count uniform
        }

        const uint32_t stage = sb + (kt % STAGES) * STAGE_SMEM;
#pragma unroll
        for (int ks = 0; ks < 2; ks++) {
            uint32_t ah[4][4], al[4][4], bh[4][2], bl[4][2];
            const uint32_t kb = ks * 32;     // 16 elems * 2B
#pragma unroll
            for (int mt = 0; mt < 4; mt++) {
                ldsm4(ah[mt], stage + 0 * TILE_SMEM + aOff + mt * 16 * ROWB + kb);
                ldsm4(al[mt], stage + 1 * TILE_SMEM + aOff + mt * 16 * ROWB + kb);
            }
#pragma unroll
            for (int p = 0; p < 2; p++) {
                uint32_t t[4];
                ldsm4(t, stage + 2 * TILE_SMEM + bOff + p * 16 * ROWB + kb);
                bh[2 * p][0] = t[0]; bh[2 * p][1] = t[1];
                bh[2 * p + 1][0] = t[2]; bh[2 * p + 1][1] = t[3];
                ldsm4(t, stage + 3 * TILE_SMEM + bOff + p * 16 * ROWB + kb);
                bl[2 * p][0] = t[0]; bl[2 * p][1] = t[1];
                bl[2 * p + 1][0] = t[2]; bl[2 * p + 1][1] = t[3];
            }
#pragma unroll
            for (int mt = 0; mt < 4; mt++)
#pragma unroll
                for (int nt = 0; nt < 4; nt++) mma16816(acc[mt][nt], ah[mt], bh[nt]);
#pragma unroll
            for (int mt = 0; mt < 4; mt++)
#pragma unroll
                for (int nt = 0; nt < 4; nt++) mma16816(acc[mt][nt], ah[mt], bl[nt]);
#pragma unroll
            for (int mt = 0; mt < 4; mt++)
#pragma unroll
                for (int nt = 0; nt < 4; nt++) mma16816(acc[mt][nt], al[mt], bh[nt]);
        }
    }

    // ---- epilogue ----
    const int mRow0 = rowBase + wm * 64 + (lane >> 2);
    const int nCol0 = colBase + wn * 32 + 2 * (lane & 3);

    if (mode == 0) {
        float* C = Cf + z * sC;
#pragma unroll
        for (int mt = 0; mt < 4; mt++) {
#pragma unroll
            for (int nt = 0; nt < 4; nt++) {
                float* c = acc[mt][nt];
                long r0 = mRow0 + mt * 16;
                int  cc = nCol0 + nt * 8;
                *(float2*)(C + r0 * ldc + cc)       = make_float2(c[0] * scale, c[1] * scale);
                *(float2*)(C + (r0 + 8) * ldc + cc) = make_float2(c[2] * scale, c[3] * scale);
            }
        }
    } else {
        __nv_bfloat16* CH = Ch + z * sC;
        __nv_bfloat16* CL = Cl + z * sC;
#pragma unroll
        for (int mt = 0; mt < 4; mt++) {
#pragma unroll
            for (int nt = 0; nt < 4; nt++) {
                float* c = acc[mt][nt];
                long r0 = mRow0 + mt * 16;
                int  cc = nCol0 + nt * 8;
#pragma unroll
                for (int h = 0; h < 2; h++) {
                    long rr = r0 + 8 * h;
                    float v0 = c[2 * h], v1 = c[2 * h + 1];
                    __nv_bfloat16 h0 = __float2bfloat16(v0);
                    __nv_bfloat16 h1 = __float2bfloat16(v1);
                    __nv_bfloat162 hp; hp.x = h0; hp.y = h1;
                    __nv_bfloat162 lp;
                    lp.x = __float2bfloat16(v0 - __bfloat162float(h0));
                    lp.y = __float2bfloat16(v1 - __bfloat162float(h1));
                    *(__nv_bfloat162*)(CH + rr * ldc + cc) = hp;
                    *(__nv_bfloat162*)(CL + rr * ldc + cc) = lp;
                }
            }
        }
    }
}

// ---------------- elementwise fp32 -> bf16 hi/lo ----------------
__global__ void __launch_bounds__(256) to_hilo(const float* __restrict__ s,
                                               __nv_bfloat16* __restrict__ h,
                                               __nv_bfloat16* __restrict__ l, int n)
{
    for (int i = blockIdx.x * 256 + threadIdx.x; i < n; i += gridDim.x * 256) {
        float v = s[i];
        __nv_bfloat16 hi = __float2bfloat16(v);
        h[i] = hi;
        l[i] = __float2bfloat16(v - __bfloat162float(hi));
    }
}

// ---------------- softmax over rows of P, emitting bf16 hi/lo ----------------
__global__ void __launch_bounds__(256) softmax_rows(const float* __restrict__ P,
                                                    __nv_bfloat16* __restrict__ Ph,
                                                    __nv_bfloat16* __restrict__ Pl)
{
    __shared__ float red[256];
    const float* p = P + (long)blockIdx.x * SEQ;
    __nv_bfloat16* ph = Ph + (long)blockIdx.x * SEQ;
    __nv_bfloat16* pl = Pl + (long)blockIdx.x * SEQ;
    const int t = threadIdx.x;

    float v[8];
    float m = -1e30f;
#pragma unroll
    for (int i = 0; i < 8; i++) { v[i] = p[t + i * 256]; m = fmaxf(m, v[i]); }
    red[t] = m; __syncthreads();
    for (int s = 128; s > 0; s >>= 1) {
        if (t < s) red[t] = fmaxf(red[t], red[t + s]);
        __syncthreads();
    }
    m = red[0]; __syncthreads();

    float sum = 0.f;
#pragma unroll
    for (int i = 0; i < 8; i++) { v[i] = __expf(v[i] - m); sum += v[i]; }
    red[t] = sum; __syncthreads();
    for (int s = 128; s > 0; s >>= 1) {
        if (t < s) red[t] += red[t + s];
        __syncthreads();
    }
    float inv = 1.0f / red[0];
#pragma unroll
    for (int i = 0; i < 8; i++) {
        float w = v[i] * inv;
        __nv_bfloat16 hi = __float2bfloat16(w);
        ph[t + i * 256] = hi;
        pl[t + i * 256] = __float2bfloat16(w - __bfloat162float(hi));
    }
}

// ---------------- host launcher ----------------
extern "C" void kernel_launch(void* const* d_in, const int* in_sizes, int n_in,
                              void* d_out, int out_size)
{
    const float* x  = (const float*)d_in[0];
    const float* Wq = (const float*)d_in[1];
    const float* Wk = (const float*)d_in[2];
    const float* Wv = (const float*)d_in[3];
    float* out = (float*)d_out;

    cudaFuncSetAttribute(gemm_tc, cudaFuncAttributeMaxDynamicSharedMemorySize, SMEM_TOTAL);

    __nv_bfloat16 *xh,*xl,*Wqh,*Wql,*Wkh,*Wkl,*Wvh,*Wvl,*Qh,*Ql,*Kh,*Kl,*Vth,*Vtl,*Ph,*Pl;
    float *P;
    cudaGetSymbolAddress((void**)&xh, g_xh);   cudaGetSymbolAddress((void**)&xl, g_xl);
    cudaGetSymbolAddress((void**)&Wqh, g_Wqh); cudaGetSymbolAddress((void**)&Wql, g_Wql);
    cudaGetSymbolAddress((void**)&Wkh, g_Wkh); cudaGetSymbolAddress((void**)&Wkl, g_Wkl);
    cudaGetSymbolAddress((void**)&Wvh, g_Wvh); cudaGetSymbolAddress((void**)&Wvl, g_Wvl);
    cudaGetSymbolAddress((void**)&Qh, g_Qh);   cudaGetSymbolAddress((void**)&Ql, g_Ql);
    cudaGetSymbolAddress((void**)&Kh, g_Kh);   cudaGetSymbolAddress((void**)&Kl, g_Kl);
    cudaGetSymbolAddress((void**)&Vth, g_Vth); cudaGetSymbolAddress((void**)&Vtl, g_Vtl);
    cudaGetSymbolAddress((void**)&P, g_P);
    cudaGetSymbolAddress((void**)&Ph, g_Ph);   cudaGetSymbolAddress((void**)&Pl, g_Pl);

    const float scale = 1.0f / sqrtf((float)DIM);

    // 1) split inputs into bf16 hi/lo
    to_hilo<<<4096, 256>>>(x,  xh,  xl,  MTOT * DIM);
    to_hilo<<<2304, 256>>>(Wq, Wqh, Wql, DIM * DIM);
    to_hilo<<<2304, 256>>>(Wk, Wkh, Wkl, DIM * DIM);
    to_hilo<<<2304, 256>>>(Wv, Wvh, Wvl, DIM * DIM);

    // 2) projections (NT): Q = x @ Wq^T, K = x @ Wk^T  -> bf16 hi/lo
    {
        dim3 g(DIM / BN, MTOT / BM, 1);
        gemm_tc<<<g, 256, SMEM_TOTAL>>>(xh, xl, Wqh, Wql, nullptr, Qh, Ql,
                                        DIM, DIM, DIM, DIM, 0, 0, 0, 1.0f, 1);
        gemm_tc<<<g, 256, SMEM_TOTAL>>>(xh, xl, Wkh, Wkl, nullptr, Kh, Kl,
                                        DIM, DIM, DIM, DIM, 0, 0, 0, 1.0f, 1);
    }
    // 3) Vt = Wv @ x^T: Vt[e, m] row-major [DIM, MTOT]
    {
        dim3 g(MTOT / BN, DIM / BM, 1);
        gemm_tc<<<g, 256, SMEM_TOTAL>>>(Wvh, Wvl, xh, xl, nullptr, Vth, Vtl,
                                        DIM, DIM, DIM, MTOT, 0, 0, 0, 1.0f, 1);
    }
    // 4) scores (batched NT): P = scale * Q @ K^T  -> fp32
    {
        dim3 g(SEQ / BN, SEQ / BM, BATCH);
        gemm_tc<<<g, 256, SMEM_TOTAL>>>(Qh, Ql, Kh, Kl, P, nullptr, nullptr,
                                        DIM, DIM, DIM, SEQ,
                                        (long)SEQ * DIM, (long)SEQ * DIM, (long)SEQ * SEQ,
                                        scale, 0);
    }
    // 5) softmax -> bf16 hi/lo
    softmax_rows<<<BATCH * SEQ, 256>>>(P, Ph, Pl);

    // 6) H = A @ V via Vt (batched NT): H[q,e] = sum_k P[q,k] * Vt[e, b*SEQ+k]
    {
        dim3 g(DIM / BN, SEQ / BM, BATCH);
        gemm_tc<<<g, 256, SMEM_TOTAL>>>(Ph, Pl, Vth, Vtl, out, nullptr, nullptr,
                                        SEQ, SEQ, MTOT, DIM,
                                        (long)SEQ * SEQ, (long)SEQ, (long)SEQ * DIM,
                                        1.0f, 0);
    }
}

// round 4
// speedup vs baseline: 4.2578x; 1.4270x over previous
#include <cuda_runtime.h>
#include <cuda_fp16.h>
#include <math.h>
#include <stdint.h>

#define BATCH 8
#define SEQ   2048
#define DIM   768
#define MTOT  (BATCH*SEQ)

// ---------------- static device scratch ----------------
__device__ __half g_xh [(size_t)MTOT*DIM];
__device__ __half g_Wqh[DIM*DIM], g_Wql[DIM*DIM];
__device__ __half g_Wkh[DIM*DIM], g_Wkl[DIM*DIM];
__device__ __half g_Wvh[DIM*DIM], g_Wvl[DIM*DIM];
__device__ __half g_Qh [(size_t)MTOT*DIM];
__device__ __half g_Kh [(size_t)MTOT*DIM], g_Kl[(size_t)MTOT*DIM];
__device__ __half g_Vth[(size_t)DIM*MTOT], g_Vtl[(size_t)DIM*MTOT];
__device__ float  g_P  [(size_t)BATCH*SEQ*SEQ];
__device__ __half g_Ph [(size_t)BATCH*SEQ*SEQ];

// ---------------- tiling ----------------
#define BM 128
#define BN 128
#define BK 32
#define STAGES 5
#define ROWB 80                        // 32 fp16 (64B) + 16B pad
#define TILE_SMEM (128*ROWB)           // 10240 B
#define STAGE_SMEM (3*TILE_SMEM)       // A, Bh, Lo = 30720 B
#define SMEM_TOTAL (STAGES*STAGE_SMEM) // 153600 B

// ---------------- PTX helpers ----------------
__device__ __forceinline__ uint32_t smem_u32(const void* p) {
    uint32_t a;
    asm("{ .reg .u64 t; cvta.to.shared.u64 t, %1; cvt.u32.u64 %0, t; }" : "=r"(a) : "l"(p));
    return a;
}
__device__ __forceinline__ void cp_async16(uint32_t saddr, const void* gaddr) {
    asm volatile("cp.async.cg.shared.global [%0], [%1], 16;" :: "r"(saddr), "l"(gaddr));
}
__device__ __forceinline__ void cp_commit() {
    asm volatile("cp.async.commit_group;" ::: "memory");
}
template<int N> __device__ __forceinline__ void cp_wait() {
    asm volatile("cp.async.wait_group %0;" :: "n"(N) : "memory");
}
__device__ __forceinline__ void ldsm4(uint32_t* r, uint32_t addr) {
    asm volatile("ldmatrix.sync.aligned.m8n8.x4.shared.b16 {%0,%1,%2,%3}, [%4];"
                 : "=r"(r[0]), "=r"(r[1]), "=r"(r[2]), "=r"(r[3]) : "r"(addr));
}
__device__ __forceinline__ void mma16816(float* c, const uint32_t* a, const uint32_t* b) {
    asm volatile(
        "mma.sync.aligned.m16n8k16.row.col.f32.f16.f16.f32 "
        "{%0,%1,%2,%3}, {%4,%5,%6,%7}, {%8,%9}, {%0,%1,%2,%3};"
        : "+f"(c[0]), "+f"(c[1]), "+f"(c[2]), "+f"(c[3])
        : "r"(a[0]), "r"(a[1]), "r"(a[2]), "r"(a[3]), "r"(b[0]), "r"(b[1]));
}

// ---------------- GEMM: C[M,N] = scale * (A@B^T + term2) ----------------
// term2 = A@Lo^T (LoSideA=false) or Lo@B^T (LoSideA=true). All operands NT, fp16.
// mode: 0 -> fp32 out (Cf, *scale), 1 -> fp16 hi+lo out (Ch, Cl), 2 -> fp16 hi only (Ch)
template<bool LoSideA>
__global__ void __launch_bounds__(256, 1) gemm_tc(
    const __half* __restrict__ A, const __half* __restrict__ B,
    const __half* __restrict__ Lo,
    float* __restrict__ Cf, __half* __restrict__ Ch, __half* __restrict__ Cl,
    int K, int lda, int ldb, int ldc,
    long sA, long sB, long sC, float scale, int mode)
{
    extern __shared__ char smem[];
    const uint32_t sb = smem_u32(smem);
    const int tid  = threadIdx.x;
    const int lane = tid & 31;
    const int wid  = tid >> 5;
    const int wm   = wid & 1;        // 2 warps along M
    const int wn   = wid >> 1;       // 4 warps along N
    const long z = blockIdx.z;

    const __half* AB  = A  + z * sA;
    const __half* BB  = B  + z * sB;
    const __half* LoB = Lo + z * (LoSideA ? sA : sB);

    const int rowBase = blockIdx.y * BM;
    const int colBase = blockIdx.x * BN;

    // ---- per-thread cp.async sources: 6 chunks of 16B per thread ----
    const __half* gsrc[6];
    uint32_t soff[6];
#pragma unroll
    for (int i = 0; i < 6; i++) {
        int g    = tid + i * 256;       // 0..1535
        int tile = g >> 9;              // 0:A 1:B 2:Lo
        int w    = g & 511;
        int row  = w >> 2;
        int ch   = w & 3;
        const __half* s;
        int rs, ld;
        if (tile == 0)      { s = AB;  rs = rowBase; ld = lda; }
        else if (tile == 1) { s = BB;  rs = colBase; ld = ldb; }
        else {
            s = LoB;
            rs = LoSideA ? rowBase : colBase;
            ld = LoSideA ? lda : ldb;
        }
        gsrc[i] = s + (long)(rs + row) * ld + ch * 8;
        soff[i] = tile * TILE_SMEM + row * ROWB + ch * 16;
    }

    // ---- per-lane ldmatrix offsets ----
    const int j = lane >> 3, r = lane & 7;
    const uint32_t aOff = (uint32_t)(wm * 64 + (j & 1) * 8 + r) * ROWB + ((j >> 1) * 8) * 2;
    const uint32_t bOff = (uint32_t)(wn * 32 + (j >> 1) * 8 + r) * ROWB + ((j & 1) * 8) * 2;

    const int kTiles = K / BK;

    // ---- prologue ----
#pragma unroll
    for (int s = 0; s < STAGES - 1; s++) {
        int k0 = s * BK;
#pragma unroll
        for (int i = 0; i < 6; i++)
            cp_async16(sb + s * STAGE_SMEM + soff[i], gsrc[i] + k0);
        cp_commit();
    }

    float acc[4][4][4];
#pragma unroll
    for (int a = 0; a < 4; a++)
#pragma unroll
        for (int b = 0; b < 4; b++)
#pragma unroll
            for (int q = 0; q < 4; q++) acc[a][b][q] = 0.f;

    for (int kt = 0; kt < kTiles; kt++) {
        cp_wait<STAGES - 2>();
        __syncthreads();

        {
            int ft = kt + STAGES - 1;
            if (ft < kTiles) {
                uint32_t sbase = sb + (ft % STAGES) * STAGE_SMEM;
                int k0 = ft * BK;
#pragma unroll
                for (int i = 0; i < 6; i++)
                    cp_async16(sbase + soff[i], gsrc[i] + k0);
            }
            cp_commit();
        }

        const uint32_t stage = sb + (kt % STAGES) * STAGE_SMEM;
#pragma unroll
        for (int ks = 0; ks < 2; ks++) {
            const uint32_t kb = ks * 32;
            uint32_t ah[4][4], bh[4][2];
#pragma unroll
            for (int mt = 0; mt < 4; mt++)
                ldsm4(ah[mt], stage + 0 * TILE_SMEM + aOff + mt * 16 * ROWB + kb);
#pragma unroll
            for (int p = 0; p < 2; p++) {
                uint32_t t[4];
                ldsm4(t, stage + 1 * TILE_SMEM + bOff + p * 16 * ROWB + kb);
                bh[2 * p][0] = t[0]; bh[2 * p][1] = t[1];
                bh[2 * p + 1][0] = t[2]; bh[2 * p + 1][1] = t[3];
            }
#pragma unroll
            for (int mt = 0; mt < 4; mt++)
#pragma unroll
                for (int nt = 0; nt < 4; nt++) mma16816(acc[mt][nt], ah[mt], bh[nt]);

            if (LoSideA) {
                uint32_t al[4][4];
#pragma unroll
                for (int mt = 0; mt < 4; mt++)
                    ldsm4(al[mt], stage + 2 * TILE_SMEM + aOff + mt * 16 * ROWB + kb);
#pragma unroll
                for (int mt = 0; mt < 4; mt++)
#pragma unroll
                    for (int nt = 0; nt < 4; nt++) mma16816(acc[mt][nt], al[mt], bh[nt]);
            } else {
                uint32_t bl[4][2];
#pragma unroll
                for (int p = 0; p < 2; p++) {
                    uint32_t t[4];
                    ldsm4(t, stage + 2 * TILE_SMEM + bOff + p * 16 * ROWB + kb);
                    bl[2 * p][0] = t[0]; bl[2 * p][1] = t[1];
                    bl[2 * p + 1][0] = t[2]; bl[2 * p + 1][1] = t[3];
                }
#pragma unroll
                for (int mt = 0; mt < 4; mt++)
#pragma unroll
                    for (int nt = 0; nt < 4; nt++) mma16816(acc[mt][nt], ah[mt], bl[nt]);
            }
        }
    }

    // ---- epilogue ----
    const int mRow0 = rowBase + wm * 64 + (lane >> 2);
    const int nCol0 = colBase + wn * 32 + 2 * (lane & 3);

    if (mode == 0) {
        float* C = Cf + z * sC;
#pragma unroll
        for (int mt = 0; mt < 4; mt++) {
#pragma unroll
            for (int nt = 0; nt < 4; nt++) {
                float* c = acc[mt][nt];
                long r0 = mRow0 + mt * 16;
                int  cc = nCol0 + nt * 8;
                *(float2*)(C + r0 * ldc + cc)       = make_float2(c[0] * scale, c[1] * scale);
                *(float2*)(C + (r0 + 8) * ldc + cc) = make_float2(c[2] * scale, c[3] * scale);
            }
        }
    } else {
        __half* CH = Ch + z * sC;
        __half* CL = Cl ? (Cl + z * sC) : nullptr;
#pragma unroll
        for (int mt = 0; mt < 4; mt++) {
#pragma unroll
            for (int nt = 0; nt < 4; nt++) {
                float* c = acc[mt][nt];
                long r0 = mRow0 + mt * 16;
                int  cc = nCol0 + nt * 8;
#pragma unroll
                for (int h = 0; h < 2; h++) {
                    long rr = r0 + 8 * h;
                    float v0 = c[2 * h], v1 = c[2 * h + 1];
                    __half h0 = __float2half(v0);
                    __half h1 = __float2half(v1);
                    __half2 hp; hp.x = h0; hp.y = h1;
                    *(__half2*)(CH + rr * ldc + cc) = hp;
                    if (mode == 1) {
                        __half2 lp;
                        lp.x = __float2half(v0 - __half2float(h0));
                        lp.y = __float2half(v1 - __half2float(h1));
                        *(__half2*)(CL + rr * ldc + cc) = lp;
                    }
                }
            }
        }
    }
}

// ---------------- conversions ----------------
__global__ void __launch_bounds__(256) to_h(const float* __restrict__ s,
                                            __half* __restrict__ h, int n)
{
    for (int i = blockIdx.x * 256 + threadIdx.x; i < n; i += gridDim.x * 256)
        h[i] = __float2half(s[i]);
}
__global__ void __launch_bounds__(256) to_hilo(const float* __restrict__ s,
                                               __half* __restrict__ h,
                                               __half* __restrict__ l, int n)
{
    for (int i = blockIdx.x * 256 + threadIdx.x; i < n; i += gridDim.x * 256) {
        float v = s[i];
        __half hi = __float2half(v);
        h[i] = hi;
        l[i] = __float2half(v - __half2float(hi));
    }
}

// ---------------- softmax over rows of P, emitting fp16 hi ----------------
__global__ void __launch_bounds__(256) softmax_rows(const float* __restrict__ P,
                                                    __half* __restrict__ Ph)
{
    __shared__ float red[256];
    const float* p = P + (long)blockIdx.x * SEQ;
    __half* ph = Ph + (long)blockIdx.x * SEQ;
    const int t = threadIdx.x;

    float v[8];
    float m = -1e30f;
#pragma unroll
    for (int i = 0; i < 8; i++) { v[i] = p[t + i * 256]; m = fmaxf(m, v[i]); }
    red[t] = m; __syncthreads();
    for (int s = 128; s > 0; s >>= 1) {
        if (t < s) red[t] = fmaxf(red[t], red[t + s]);
        __syncthreads();
    }
    m = red[0]; __syncthreads();

    float sum = 0.f;
#pragma unroll
    for (int i = 0; i < 8; i++) { v[i] = __expf(v[i] - m); sum += v[i]; }
    red[t] = sum; __syncthreads();
    for (int s = 128; s > 0; s >>= 1) {
        if (t < s) red[t] += red[t + s];
        __syncthreads();
    }
    float inv = 1.0f / red[0];
#pragma unroll
    for (int i = 0; i < 8; i++)
        ph[t + i * 256] = __float2half(v[i] * inv);
}

// ---------------- host launcher ----------------
extern "C" void kernel_launch(void* const* d_in, const int* in_sizes, int n_in,
                              void* d_out, int out_size)
{
    const float* x  = (const float*)d_in[0];
    const float* Wq = (const float*)d_in[1];
    const float* Wk = (const float*)d_in[2];
    const float* Wv = (const float*)d_in[3];
    float* out = (float*)d_out;

    cudaFuncSetAttribute(gemm_tc<false>, cudaFuncAttributeMaxDynamicSharedMemorySize, SMEM_TOTAL);
    cudaFuncSetAttribute(gemm_tc<true>,  cudaFuncAttributeMaxDynamicSharedMemorySize, SMEM_TOTAL);

    __half *xh,*Wqh,*Wql,*Wkh,*Wkl,*Wvh,*Wvl,*Qh,*Kh,*Kl,*Vth,*Vtl,*Ph;
    float *P;
    cudaGetSymbolAddress((void**)&xh, g_xh);
    cudaGetSymbolAddress((void**)&Wqh, g_Wqh); cudaGetSymbolAddress((void**)&Wql, g_Wql);
    cudaGetSymbolAddress((void**)&Wkh, g_Wkh); cudaGetSymbolAddress((void**)&Wkl, g_Wkl);
    cudaGetSymbolAddress((void**)&Wvh, g_Wvh); cudaGetSymbolAddress((void**)&Wvl, g_Wvl);
    cudaGetSymbolAddress((void**)&Qh, g_Qh);
    cudaGetSymbolAddress((void**)&Kh, g_Kh);   cudaGetSymbolAddress((void**)&Kl, g_Kl);
    cudaGetSymbolAddress((void**)&Vth, g_Vth); cudaGetSymbolAddress((void**)&Vtl, g_Vtl);
    cudaGetSymbolAddress((void**)&P, g_P);
    cudaGetSymbolAddress((void**)&Ph, g_Ph);

    const float scale = 1.0f / sqrtf((float)DIM);

    // 1) convert inputs
    to_h   <<<4096, 256>>>(x,  xh,  MTOT * DIM);
    to_hilo<<<2304, 256>>>(Wq, Wqh, Wql, DIM * DIM);
    to_hilo<<<2304, 256>>>(Wk, Wkh, Wkl, DIM * DIM);
    to_hilo<<<2304, 256>>>(Wv, Wvh, Wvl, DIM * DIM);

    // 2) Q = x@Wq^T (hi only), K = x@Wk^T (hi+lo)  [Lo on B side]
    {
        dim3 g(DIM / BN, MTOT / BM, 1);
        gemm_tc<false><<<g, 256, SMEM_TOTAL>>>(xh, Wqh, Wql, nullptr, Qh, nullptr,
                                               DIM, DIM, DIM, DIM, 0, 0, 0, 1.0f, 2);
        gemm_tc<false><<<g, 256, SMEM_TOTAL>>>(xh, Wkh, Wkl, nullptr, Kh, Kl,
                                               DIM, DIM, DIM, DIM, 0, 0, 0, 1.0f, 1);
    }
    // 3) Vt = Wv@x^T (hi+lo), Lo on A side (Wvl)
    {
        dim3 g(MTOT / BN, DIM / BM, 1);
        gemm_tc<true><<<g, 256, SMEM_TOTAL>>>(Wvh, xh, Wvl, nullptr, Vth, Vtl,
                                              DIM, DIM, DIM, MTOT, 0, 0, 0, 1.0f, 1);
    }
    // 4) scores = scale * Q@K^T -> fp32  [Lo = Kl on B side]
    {
        dim3 g(SEQ / BN, SEQ / BM, BATCH);
        gemm_tc<false><<<g, 256, SMEM_TOTAL>>>(Qh, Kh, Kl, P, nullptr, nullptr,
                                               DIM, DIM, DIM, SEQ,
                                               (long)SEQ * DIM, (long)SEQ * DIM,
                                               (long)SEQ * SEQ, scale, 0);
    }
    // 5) softmax -> fp16 hi
    softmax_rows<<<BATCH * SEQ, 256>>>(P, Ph);

    // 6) H = P@Vt -> fp32 out  [Lo = Vtl on B side; batch offsets: A rows, B k-offset]
    {
        dim3 g(DIM / BN, SEQ / BM, BATCH);
        gemm_tc<false><<<g, 256, SMEM_TOTAL>>>(Ph, Vth, Vtl, out, nullptr, nullptr,
                                               SEQ, SEQ, MTOT, DIM,
                                               (long)SEQ * SEQ, (long)SEQ,
                                               (long)SEQ * DIM, 1.0f, 0);
    }
}

// round 5
// speedup vs baseline: 4.4332x; 1.0412x over previous
#include <cuda_runtime.h>
#include <cuda_fp16.h>
#include <math.h>
#include <stdint.h>

#define BATCH 8
#define SEQ   2048
#define DIM   768
#define MTOT  (BATCH*SEQ)

// ---------------- static device scratch ----------------
__device__ __half g_xh [(size_t)MTOT*DIM];
__device__ __half g_Wqh[DIM*DIM], g_Wql[DIM*DIM];
__device__ __half g_Wkh[DIM*DIM], g_Wkl[DIM*DIM];
__device__ __half g_Wvh[DIM*DIM], g_Wvl[DIM*DIM];
__device__ __half g_Qh [(size_t)MTOT*DIM];
__device__ __half g_Kh [(size_t)MTOT*DIM], g_Kl[(size_t)MTOT*DIM];
__device__ __half g_Vth[(size_t)DIM*MTOT], g_Vtl[(size_t)DIM*MTOT];
__device__ float  g_P  [(size_t)BATCH*SEQ*SEQ];
__device__ __half g_Ph [(size_t)BATCH*SEQ*SEQ];

// ---------------- tiling ----------------
#define BM 128
#define BN 128
#define BK 64
#define STAGES 3
#define ROWB 144                       // 64 fp16 (128B) + 16B pad
#define TILE_SMEM (128*ROWB)           // 18432 B
#define STAGE_SMEM (3*TILE_SMEM)       // A, B, Lo = 55296 B
#define SMEM_TOTAL (STAGES*STAGE_SMEM) // 165888 B

// ---------------- PTX helpers ----------------
__device__ __forceinline__ uint32_t smem_u32(const void* p) {
    uint32_t a;
    asm("{ .reg .u64 t; cvta.to.shared.u64 t, %1; cvt.u32.u64 %0, t; }" : "=r"(a) : "l"(p));
    return a;
}
__device__ __forceinline__ void cp_async16(uint32_t saddr, const void* gaddr) {
    asm volatile("cp.async.cg.shared.global [%0], [%1], 16;" :: "r"(saddr), "l"(gaddr));
}
__device__ __forceinline__ void cp_commit() {
    asm volatile("cp.async.commit_group;" ::: "memory");
}
template<int N> __device__ __forceinline__ void cp_wait() {
    asm volatile("cp.async.wait_group %0;" :: "n"(N) : "memory");
}
__device__ __forceinline__ void ldsm4(uint32_t* r, uint32_t addr) {
    asm volatile("ldmatrix.sync.aligned.m8n8.x4.shared.b16 {%0,%1,%2,%3}, [%4];"
                 : "=r"(r[0]), "=r"(r[1]), "=r"(r[2]), "=r"(r[3]) : "r"(addr));
}
__device__ __forceinline__ void mma16816(float* c, const uint32_t* a, const uint32_t* b) {
    asm volatile(
        "mma.sync.aligned.m16n8k16.row.col.f32.f16.f16.f32 "
        "{%0,%1,%2,%3}, {%4,%5,%6,%7}, {%8,%9}, {%0,%1,%2,%3};"
        : "+f"(c[0]), "+f"(c[1]), "+f"(c[2]), "+f"(c[3])
        : "r"(a[0]), "r"(a[1]), "r"(a[2]), "r"(a[3]), "r"(b[0]), "r"(b[1]));
}

// ---------------- GEMM: C[M,N] = scale * (A@B^T + term2), fp16 NT ----------------
// term2 = Lo@B^T (LoSideA) else A@Lo^T.
// mode: 0 -> fp32 out (*scale), 1 -> fp16 hi+lo out, 2 -> fp16 hi only
// QKF: gridDim.z=2 selects (Wq -> Qh, mode2) / (Wk -> Kh+Kl, mode1); B/Lo/C args ignored.
template<bool LoSideA, bool QKF>
__global__ void __launch_bounds__(256, 1) gemm_tc(
    const __half* __restrict__ A, const __half* __restrict__ Bp,
    const __half* __restrict__ Lop,
    float* __restrict__ Cf, __half* __restrict__ Chp, __half* __restrict__ Clp,
    int K, int lda, int ldb, int ldc,
    long sA, long sB, long sC, float scale, int mode)
{
    extern __shared__ char smem[];
    const uint32_t sb = smem_u32(smem);
    const int tid  = threadIdx.x;
    const int lane = tid & 31;
    const int wid  = tid >> 5;
    const int wm   = wid & 1;
    const int wn   = wid >> 1;
    const long z = blockIdx.z;

    const __half* AB  = A + (QKF ? 0 : z * sA);
    const __half* BB;
    const __half* LoB;
    __half* Ch;
    __half* Cl;
    if (QKF) {
        BB  = (z == 0) ? g_Wqh : g_Wkh;
        LoB = (z == 0) ? g_Wql : g_Wkl;
        Ch  = (z == 0) ? g_Qh  : g_Kh;
        Cl  = g_Kl;
        mode = (z == 0) ? 2 : 1;
    } else {
        BB  = Bp  + z * sB;
        LoB = Lop + z * (LoSideA ? sA : sB);
        Ch  = Chp ? Chp + z * sC : nullptr;
        Cl  = Clp ? Clp + z * sC : nullptr;
    }

    const int rowBase = blockIdx.y * BM;
    const int colBase = blockIdx.x * BN;

    // ---- cp.async: 12 x 16B chunks per thread per stage ----
    const __half* gsrc[12];
    uint32_t soff[12];
#pragma unroll
    for (int i = 0; i < 12; i++) {
        int idx  = tid + i * 256;          // 0..3071
        int tile = idx >> 10;              // 0:A 1:B 2:Lo
        int w    = idx & 1023;
        int row  = w >> 3;
        int ch   = w & 7;
        const __half* s;
        int rs, ld;
        if (tile == 0)      { s = AB;  rs = rowBase; ld = lda; }
        else if (tile == 1) { s = BB;  rs = colBase; ld = ldb; }
        else {
            s  = LoB;
            rs = LoSideA ? rowBase : colBase;
            ld = LoSideA ? lda : ldb;
        }
        gsrc[i] = s + (long)(rs + row) * ld + ch * 8;
        soff[i] = tile * TILE_SMEM + row * ROWB + ch * 16;
    }

    // ---- ldmatrix lane offsets ----
    const int j = lane >> 3, r = lane & 7;
    const uint32_t aOff = (uint32_t)(wm * 64 + (j & 1) * 8 + r) * ROWB + ((j >> 1) * 8) * 2;
    const uint32_t bOff = (uint32_t)(wn * 32 + (j >> 1) * 8 + r) * ROWB + ((j & 1) * 8) * 2;

    const int kTiles = K / BK;

    // ---- prologue: fill STAGES-1 stages ----
#pragma unroll
    for (int s = 0; s < STAGES - 1; s++) {
        int k0 = s * BK;
#pragma unroll
        for (int i = 0; i < 12; i++)
            cp_async16(sb + s * STAGE_SMEM + soff[i], gsrc[i] + k0);
        cp_commit();
    }

    float acc[4][4][4];
#pragma unroll
    for (int a = 0; a < 4; a++)
#pragma unroll
        for (int b = 0; b < 4; b++)
#pragma unroll
            for (int q = 0; q < 4; q++) acc[a][b][q] = 0.f;

    // fragment double buffers
    uint32_t ah[2][4][4], bh[2][4][2], lo[2][4][4];   // lo uses [4][2] shape when !LoSideA

    for (int kt = 0; kt < kTiles; kt++) {
        cp_wait<STAGES - 2>();
        __syncthreads();

        {
            int ft = kt + STAGES - 1;
            if (ft < kTiles) {
                uint32_t sbase = sb + (ft % STAGES) * STAGE_SMEM;
                int k0 = ft * BK;
#pragma unroll
                for (int i = 0; i < 12; i++)
                    cp_async16(sbase + soff[i], gsrc[i] + k0);
            }
            cp_commit();
        }

        const uint32_t stage = sb + (kt % STAGES) * STAGE_SMEM;

        // load fragments for a k-step into buffer b
#define LOAD_FRAGS(ks, bi)                                                        \
        do {                                                                      \
            const uint32_t kb = (ks) * 32;                                        \
            _Pragma("unroll")                                                     \
            for (int mt = 0; mt < 4; mt++)                                        \
                ldsm4(ah[bi][mt], stage + 0 * TILE_SMEM + aOff + mt * 16 * ROWB + kb); \
            _Pragma("unroll")                                                     \
            for (int p = 0; p < 2; p++) {                                         \
                uint32_t t[4];                                                    \
                ldsm4(t, stage + 1 * TILE_SMEM + bOff + p * 16 * ROWB + kb);      \
                bh[bi][2 * p][0] = t[0]; bh[bi][2 * p][1] = t[1];                 \
                bh[bi][2 * p + 1][0] = t[2]; bh[bi][2 * p + 1][1] = t[3];         \
            }                                                                     \
            if (LoSideA) {                                                        \
                _Pragma("unroll")                                                 \
                for (int mt = 0; mt < 4; mt++)                                    \
                    ldsm4(lo[bi][mt], stage + 2 * TILE_SMEM + aOff + mt * 16 * ROWB + kb); \
            } else {                                                              \
                _Pragma("unroll")                                                 \
                for (int p = 0; p < 2; p++) {                                     \
                    uint32_t t[4];                                                \
                    ldsm4(t, stage + 2 * TILE_SMEM + bOff + p * 16 * ROWB + kb);  \
                    lo[bi][2 * p][0] = t[0]; lo[bi][2 * p][1] = t[1];             \
                    lo[bi][2 * p + 1][0] = t[2]; lo[bi][2 * p + 1][1] = t[3];     \
                }                                                                 \
            }                                                                     \
        } while (0)

        LOAD_FRAGS(0, 0);
#pragma unroll
        for (int ks = 0; ks < 4; ks++) {
            const int cur = ks & 1;
            if (ks < 3) LOAD_FRAGS(ks + 1, (ks + 1) & 1);
#pragma unroll
            for (int mt = 0; mt < 4; mt++)
#pragma unroll
                for (int nt = 0; nt < 4; nt++)
                    mma16816(acc[mt][nt], ah[cur][mt], bh[cur][nt]);
            if (LoSideA) {
#pragma unroll
                for (int mt = 0; mt < 4; mt++)
#pragma unroll
                    for (int nt = 0; nt < 4; nt++)
                        mma16816(acc[mt][nt], lo[cur][mt], bh[cur][nt]);
            } else {
#pragma unroll
                for (int mt = 0; mt < 4; mt++)
#pragma unroll
                    for (int nt = 0; nt < 4; nt++)
                        mma16816(acc[mt][nt], ah[cur][mt], lo[cur][nt]);
            }
        }
#undef LOAD_FRAGS
    }

    // ---- epilogue ----
    const int mRow0 = rowBase + wm * 64 + (lane >> 2);
    const int nCol0 = colBase + wn * 32 + 2 * (lane & 3);

    if (mode == 0) {
        float* C = Cf + z * sC;
#pragma unroll
        for (int mt = 0; mt < 4; mt++) {
#pragma unroll
            for (int nt = 0; nt < 4; nt++) {
                float* c = acc[mt][nt];
                long r0 = mRow0 + mt * 16;
                int  cc = nCol0 + nt * 8;
                *(float2*)(C + r0 * ldc + cc)       = make_float2(c[0] * scale, c[1] * scale);
                *(float2*)(C + (r0 + 8) * ldc + cc) = make_float2(c[2] * scale, c[3] * scale);
            }
        }
    } else {
#pragma unroll
        for (int mt = 0; mt < 4; mt++) {
#pragma unroll
            for (int nt = 0; nt < 4; nt++) {
                float* c = acc[mt][nt];
                long r0 = mRow0 + mt * 16;
                int  cc = nCol0 + nt * 8;
#pragma unroll
                for (int h = 0; h < 2; h++) {
                    long rr = r0 + 8 * h;
                    float v0 = c[2 * h], v1 = c[2 * h + 1];
                    __half h0 = __float2half(v0);
                    __half h1 = __float2half(v1);
                    __half2 hp; hp.x = h0; hp.y = h1;
                    *(__half2*)(Ch + rr * ldc + cc) = hp;
                    if (mode == 1) {
                        __half2 lp;
                        lp.x = __float2half(v0 - __half2float(h0));
                        lp.y = __float2half(v1 - __half2float(h1));
                        *(__half2*)(Cl + rr * ldc + cc) = lp;
                    }
                }
            }
        }
    }
}

// ---------------- conversions ----------------
__global__ void __launch_bounds__(256) to_h(const float* __restrict__ s,
                                            __half* __restrict__ h, int n)
{
    for (int i = blockIdx.x * 256 + threadIdx.x; i < n; i += gridDim.x * 256)
        h[i] = __float2half(s[i]);
}
__global__ void __launch_bounds__(256) to_hilo(const float* __restrict__ s,
                                               __half* __restrict__ h,
                                               __half* __restrict__ l, int n)
{
    for (int i = blockIdx.x * 256 + threadIdx.x; i < n; i += gridDim.x * 256) {
        float v = s[i];
        __half hi = __float2half(v);
        h[i] = hi;
        l[i] = __float2half(v - __half2float(hi));
    }
}

// ---------------- softmax ----------------
__global__ void __launch_bounds__(256) softmax_rows(const float* __restrict__ P,
                                                    __half* __restrict__ Ph)
{
    __shared__ float red[256];
    const float* p = P + (long)blockIdx.x * SEQ;
    __half* ph = Ph + (long)blockIdx.x * SEQ;
    const int t = threadIdx.x;

    float v[8];
    float m = -1e30f;
#pragma unroll
    for (int i = 0; i < 8; i++) { v[i] = p[t + i * 256]; m = fmaxf(m, v[i]); }
    red[t] = m; __syncthreads();
    for (int s = 128; s > 0; s >>= 1) {
        if (t < s) red[t] = fmaxf(red[t], red[t + s]);
        __syncthreads();
    }
    m = red[0]; __syncthreads();

    float sum = 0.f;
#pragma unroll
    for (int i = 0; i < 8; i++) { v[i] = __expf(v[i] - m); sum += v[i]; }
    red[t] = sum; __syncthreads();
    for (int s = 128; s > 0; s >>= 1) {
        if (t < s) red[t] += red[t + s];
        __syncthreads();
    }
    float inv = 1.0f / red[0];
#pragma unroll
    for (int i = 0; i < 8; i++)
        ph[t + i * 256] = __float2half(v[i] * inv);
}

// ---------------- host launcher ----------------
extern "C" void kernel_launch(void* const* d_in, const int* in_sizes, int n_in,
                              void* d_out, int out_size)
{
    const float* x  = (const float*)d_in[0];
    const float* Wq = (const float*)d_in[1];
    const float* Wk = (const float*)d_in[2];
    const float* Wv = (const float*)d_in[3];
    float* out = (float*)d_out;

    cudaFuncSetAttribute((const void*)gemm_tc<false, false>, cudaFuncAttributeMaxDynamicSharedMemorySize, SMEM_TOTAL);
    cudaFuncSetAttribute((const void*)gemm_tc<false, true>,  cudaFuncAttributeMaxDynamicSharedMemorySize, SMEM_TOTAL);
    cudaFuncSetAttribute((const void*)gemm_tc<true,  false>, cudaFuncAttributeMaxDynamicSharedMemorySize, SMEM_TOTAL);

    __half *xh,*Wqh,*Wql,*Wkh,*Wkl,*Wvh,*Wvl,*Qh,*Kh,*Kl,*Vth,*Vtl,*Ph;
    float *P;
    cudaGetSymbolAddress((void**)&xh, g_xh);
    cudaGetSymbolAddress((void**)&Wqh, g_Wqh); cudaGetSymbolAddress((void**)&Wql, g_Wql);
    cudaGetSymbolAddress((void**)&Wkh, g_Wkh); cudaGetSymbolAddress((void**)&Wkl, g_Wkl);
    cudaGetSymbolAddress((void**)&Wvh, g_Wvh); cudaGetSymbolAddress((void**)&Wvl, g_Wvl);
    cudaGetSymbolAddress((void**)&Qh, g_Qh);
    cudaGetSymbolAddress((void**)&Kh, g_Kh);   cudaGetSymbolAddress((void**)&Kl, g_Kl);
    cudaGetSymbolAddress((void**)&Vth, g_Vth); cudaGetSymbolAddress((void**)&Vtl, g_Vtl);
    cudaGetSymbolAddress((void**)&P, g_P);
    cudaGetSymbolAddress((void**)&Ph, g_Ph);

    const float scale = 1.0f / sqrtf((float)DIM);

    // 1) conversions
    to_h   <<<4096, 256>>>(x,  xh,  MTOT * DIM);
    to_hilo<<<2304, 256>>>(Wq, Wqh, Wql, DIM * DIM);
    to_hilo<<<2304, 256>>>(Wk, Wkh, Wkl, DIM * DIM);
    to_hilo<<<2304, 256>>>(Wv, Wvh, Wvl, DIM * DIM);

    // 2) fused Q&K projections (z=0 -> Q hi, z=1 -> K hi+lo)
    {
        dim3 g(DIM / BN, MTOT / BM, 2);
        gemm_tc<false, true><<<g, 256, SMEM_TOTAL>>>(xh, nullptr, nullptr,
                                                     nullptr, nullptr, nullptr,
                                                     DIM, DIM, DIM, DIM, 0, 0, 0, 1.0f, 0);
    }
    // 3) Vt = Wv@x^T (hi+lo), Lo on A side
    {
        dim3 g(MTOT / BN, DIM / BM, 1);
        gemm_tc<true, false><<<g, 256, SMEM_TOTAL>>>(Wvh, xh, Wvl, nullptr, Vth, Vtl,
                                                     DIM, DIM, DIM, MTOT, 0, 0, 0, 1.0f, 1);
    }
    // 4) scores = scale * Q@K^T -> fp32
    {
        dim3 g(SEQ / BN, SEQ / BM, BATCH);
        gemm_tc<false, false><<<g, 256, SMEM_TOTAL>>>(Qh, Kh, Kl, P, nullptr, nullptr,
                                                      DIM, DIM, DIM, SEQ,
                                                      (long)SEQ * DIM, (long)SEQ * DIM,
                                                      (long)SEQ * SEQ, scale, 0);
    }
    // 5) softmax -> fp16
    softmax_rows<<<BATCH * SEQ, 256>>>(P, Ph);

    // 6) H = P@Vt -> fp32 out
    {
        dim3 g(DIM / BN, SEQ / BM, BATCH);
        gemm_tc<false, false><<<g, 256, SMEM_TOTAL>>>(Ph, Vth, Vtl, out, nullptr, nullptr,
                                                      SEQ, SEQ, MTOT, DIM,
                                                      (long)SEQ * SEQ, (long)SEQ,
                                                      (long)SEQ * DIM, 1.0f, 0);
    }
}